// round 15
// baseline (speedup 1.0000x reference)
#include <cuda_runtime.h>
#include <cuda_bf16.h>
#include <cstdint>

#define B_ 512
#define T_ 64
#define D_ 512
#define H_ 256
#define A_ 256
#define C_ 96
#define STEPS_ 26
#define H3_ 768

// ---------------- device scratch ----------------
__device__ __nv_bfloat16 g_xProjT[(size_t)B_ * A_ * T_];   // [B, A, T] bf16
__device__ float g_h[B_ * H_];
__device__ float g_sp[B_ * A_];
__device__ float g_gi[B_ * H3_];
__device__ float g_gh[B_ * H3_];
__device__ float g_WsT[H_ * A_];
__device__ float g_WfcT[H_ * C_];
__device__ float g_WihEmbT[A_ * H3_];
__device__ float g_embProj[(C_ + 1) * H3_];
__device__ __nv_bfloat16 g_WxHi[A_ * D_],  g_WxLo[A_ * D_];
__device__ __nv_bfloat16 g_WicHi[H3_ * D_], g_WicLo[H3_ * D_];
__device__ __nv_bfloat16 g_WhhHi[H3_ * H_], g_WhhLo[H3_ * H_];
__device__ __nv_bfloat16 g_ctxHi[B_ * D_],  g_ctxLo[B_ * D_];
__device__ __nv_bfloat16 g_hHi[B_ * H_],   g_hLo[B_ * H_];

// ---------------- math helpers ----------------
__device__ __forceinline__ float fma_tanh(float x) {
    x = fminf(3.2f, fmaxf(-3.2f, x));
    float u = x * x;
    float num = x * (945.0f + u * (105.0f + u));
    float den = 945.0f + u * (420.0f + u * 15.0f);
    float y = 1.0582e-3f + u * (-2.1408e-4f + u * 1.2184e-5f);
    y = y * (2.0f - den * y);
    y = y * (2.0f - den * y);
    y = y * (2.0f - den * y);
    return num * y;
}
__device__ __forceinline__ float fma_sigmoid(float x) {
    return 0.5f + 0.5f * fma_tanh(0.5f * x);
}
// score tanh: args tightly bounded -> clamp 1.5, CF-Pade [105+10u]/[105+45u+u^2]
__device__ __forceinline__ float tanh_s(float x) {
    x = fminf(1.5f, fmaxf(-1.5f, x));
    float u = x * x;
    float num = 105.0f + 10.0f * u;
    float den = 105.0f + u * (45.0f + u);
    float y = 9.5238e-3f + u * (-3.5187e-3f + 6.1742e-4f * u);
    y = y * (2.0f - den * y);
    y = y * (2.0f - den * y);
    return x * num * y;
}
__device__ __forceinline__ float warp_sum(float v) {
    #pragma unroll
    for (int o = 16; o; o >>= 1) v += __shfl_xor_sync(0xffffffffu, v, o);
    return v;
}
__device__ __forceinline__ float warp_max(float v) {
    #pragma unroll
    for (int o = 16; o; o >>= 1) v = fmaxf(v, __shfl_xor_sync(0xffffffffu, v, o));
    return v;
}

// ---------------- mma helpers ----------------
__device__ __forceinline__ uint32_t smem_addr_u32(const void* p) {
    uint32_t a;
    asm("{ .reg .u64 t; cvta.to.shared.u64 t, %1; cvt.u32.u64 %0, t; }" : "=r"(a) : "l"(p));
    return a;
}
__device__ __forceinline__ void ldsm4(uint32_t a[4], uint32_t addr) {
    asm volatile("ldmatrix.sync.aligned.m8n8.x4.shared.b16 {%0,%1,%2,%3}, [%4];"
        : "=r"(a[0]), "=r"(a[1]), "=r"(a[2]), "=r"(a[3]) : "r"(addr));
}
__device__ __forceinline__ void ldsm2(uint32_t b[2], uint32_t addr) {
    asm volatile("ldmatrix.sync.aligned.m8n8.x2.shared.b16 {%0,%1}, [%2];"
        : "=r"(b[0]), "=r"(b[1]) : "r"(addr));
}
__device__ __forceinline__ void mma16816(float c[4], const uint32_t a[4], const uint32_t b[2]) {
    asm volatile("mma.sync.aligned.m16n8k16.row.col.f32.bf16.bf16.f32 "
        "{%0,%1,%2,%3}, {%4,%5,%6,%7}, {%8,%9}, {%0,%1,%2,%3};"
        : "+f"(c[0]), "+f"(c[1]), "+f"(c[2]), "+f"(c[3])
        : "r"(a[0]), "r"(a[1]), "r"(a[2]), "r"(a[3]), "r"(b[0]), "r"(b[1]));
}
#define SWZ(o) ((o) ^ (((o) >> 3) & 0x70))

__device__ __forceinline__ void split_f8(const float* v, uint4& hi, uint4& lo) {
    __nv_bfloat162* hp = (__nv_bfloat162*)&hi;
    __nv_bfloat162* lp = (__nv_bfloat162*)&lo;
    #pragma unroll
    for (int j = 0; j < 4; j++) {
        float x = v[2 * j], y = v[2 * j + 1];
        __nv_bfloat16 hx = __float2bfloat16(x), hy = __float2bfloat16(y);
        hp[j].x = hx; hp[j].y = hy;
        lp[j].x = __float2bfloat16(x - __bfloat162float(hx));
        lp[j].y = __float2bfloat16(y - __bfloat162float(hy));
    }
}

// ---------------- shared-mem layouts ----------------
struct GemmBuf {                       // 32 KB
    __nv_bfloat16 tA[2][64 * 64];
    __nv_bfloat16 tB[2][64 * 64];
};
struct CtxBuf {
    float sp[A_];
    float ww[A_];
    float part[64][33];                // score partials [t][a-group]; reused as float4 tmp
    float vb[T_];
    float al[T_];
};
union SMU { GemmBuf g; CtxBuf c; };

// ---------------- 64x64 tile GEMM ----------------
__device__ __forceinline__ void tile_gemm64(GemmBuf* s,
    const __nv_bfloat16* __restrict__ Ahi, const __nv_bfloat16* __restrict__ Alo, int lda,
    const __nv_bfloat16* __restrict__ Bhi, const __nv_bfloat16* __restrict__ Blo, int ldb,
    int m0, int n0, int kch, float* __restrict__ Cout)
{
    const int tid = threadIdx.x;
    const int lane = tid & 31;
    const int w = tid >> 5;
    const int wm = (w & 1) * 32;
    const int wn = (w >> 1) * 16;
    uint32_t sa = smem_addr_u32(s->tA);
    uint32_t sb = smem_addr_u32(s->tB);
    char* pa = (char*)s->tA;
    char* pb = (char*)s->tB;

    float acc[2][2][4] = {};
    for (int c = 0; c < kch; c++) {
        const int k0 = c * 64;
        __syncthreads();
        #pragma unroll
        for (int i = tid; i < 512; i += 256) {
            int r = i >> 3, j8 = i & 7;
            uint32_t off = SWZ((uint32_t)(r * 128 + j8 * 16));
            *(uint4*)(pa + off)        = *(const uint4*)(Ahi + (size_t)(m0 + r) * lda + k0 + j8 * 8);
            *(uint4*)(pa + 8192 + off) = *(const uint4*)(Alo + (size_t)(m0 + r) * lda + k0 + j8 * 8);
            *(uint4*)(pb + off)        = *(const uint4*)(Bhi + (size_t)(n0 + r) * ldb + k0 + j8 * 8);
            *(uint4*)(pb + 8192 + off) = *(const uint4*)(Blo + (size_t)(n0 + r) * ldb + k0 + j8 * 8);
        }
        __syncthreads();

        #pragma unroll
        for (int ks = 0; ks < 4; ks++) {
            uint32_t bh[2][2], bl[2][2];
            #pragma unroll
            for (int nj = 0; nj < 2; nj++) {
                int rr = wn + nj * 8 + (lane & 7);
                uint32_t cb = (uint32_t)(ks * 32 + ((lane >> 3) & 1) * 16);
                uint32_t ad = SWZ((uint32_t)(rr * 128) + cb);
                ldsm2(bh[nj], sb + ad);
                ldsm2(bl[nj], sb + 8192 + ad);
            }
            #pragma unroll
            for (int mi = 0; mi < 2; mi++) {
                int rr = wm + mi * 16 + (lane & 15);
                uint32_t cb = (uint32_t)(ks * 32 + (lane >> 4) * 16);
                uint32_t ad = SWZ((uint32_t)(rr * 128) + cb);
                uint32_t ah[4], al[4];
                ldsm4(ah, sa + ad);
                ldsm4(al, sa + 8192 + ad);
                #pragma unroll
                for (int nj = 0; nj < 2; nj++) {
                    mma16816(acc[mi][nj], ah, bh[nj]);
                    mma16816(acc[mi][nj], al, bh[nj]);
                    mma16816(acc[mi][nj], ah, bl[nj]);
                }
            }
        }
    }

    #pragma unroll
    for (int mi = 0; mi < 2; mi++) {
        int mr = m0 + wm + mi * 16 + (lane >> 2);
        #pragma unroll
        for (int nj = 0; nj < 2; nj++) {
            int nc = n0 + wn + nj * 8 + (lane & 3) * 2;
            float2 o0 = {acc[mi][nj][0], acc[mi][nj][1]};
            float2 o1 = {acc[mi][nj][2], acc[mi][nj][3]};
            *(float2*)(Cout + (size_t)mr * H3_ + nc) = o0;
            *(float2*)(Cout + (size_t)(mr + 8) * H3_ + nc) = o1;
        }
    }
}

// ---------------- setup ----------------
__global__ void setup_kernel(const float* __restrict__ Ws,
                             const float* __restrict__ Wfc,
                             const float* __restrict__ Wih,
                             const float* __restrict__ Wx,
                             const float* __restrict__ Whh) {
    int idx = blockIdx.x * 256 + threadIdx.x;
    int stride = gridDim.x * 256;
    for (int i = idx; i < B_ * H_; i += stride) {
        g_h[i] = 0.0f;
        g_hHi[i] = __float2bfloat16(0.0f);
        g_hLo[i] = __float2bfloat16(0.0f);
    }
    for (int i = idx; i < H_ * A_; i += stride) {
        int k = i >> 8, a = i & 255;
        g_WsT[i] = Ws[a * H_ + k];
    }
    for (int i = idx; i < H_ * C_; i += stride) {
        int k = i / C_, c = i - k * C_;
        g_WfcT[i] = Wfc[c * H_ + k];
    }
    for (int i = idx; i < A_ * H3_; i += stride) {
        int k = i / H3_, n = i - k * H3_;
        g_WihEmbT[i] = Wih[n * (D_ + A_) + k];
    }
    for (int i = idx; i < A_ * D_; i += stride) {
        float x = Wx[i];
        __nv_bfloat16 h = __float2bfloat16(x);
        g_WxHi[i] = h;
        g_WxLo[i] = __float2bfloat16(x - __bfloat162float(h));
    }
    for (int i = idx; i < H3_ * D_; i += stride) {
        int n = i >> 9, k = i & 511;
        float x = Wih[n * (D_ + A_) + A_ + k];
        __nv_bfloat16 h = __float2bfloat16(x);
        g_WicHi[i] = h;
        g_WicLo[i] = __float2bfloat16(x - __bfloat162float(h));
    }
    for (int i = idx; i < H3_ * H_; i += stride) {
        float x = Whh[i];
        __nv_bfloat16 h = __float2bfloat16(x);
        g_WhhHi[i] = h;
        g_WhhLo[i] = __float2bfloat16(x - __bfloat162float(h));
    }
}

__global__ __launch_bounds__(256) void embproj_kernel(const float* __restrict__ emb,
                                                      const float* __restrict__ bih) {
    __shared__ float es[A_];
    int y = blockIdx.x, tid = threadIdx.x;
    es[tid] = emb[y * A_ + tid];
    __syncthreads();
    for (int nn = tid; nn < H3_; nn += 256) {
        float acc = bih[nn];
        #pragma unroll 8
        for (int k = 0; k < A_; k++) acc += g_WihEmbT[k * H3_ + nn] * es[k];
        g_embProj[y * H3_ + nn] = acc;
    }
}

// ---------------- xproj (mma.sync, M=128/N=128, inline A split, bf16 output) ----
#define MM_AHI 0
#define MM_ALO 16384
#define MM_BHI 32768
#define MM_BLO 49152
#define MM_DYN (65536 + 1024)

__global__ __launch_bounds__(256, 1) void xproj_mma_kernel(const float* __restrict__ img,
                                                           const float* __restrict__ bx) {
    extern __shared__ char dynsm[];
    __shared__ float s_bx[128];
    const int tid = threadIdx.x;
    const int lane = tid & 31;
    const int w = tid >> 5;
    const int n0 = blockIdx.x * 128;
    const int m0 = blockIdx.y * 128;

    uint32_t dynb = smem_addr_u32(dynsm);
    uint32_t smb = (dynb + 1023) & ~1023u;
    char* sm = dynsm + (smb - dynb);

    if (tid < 128) s_bx[tid] = bx[n0 + tid];

    const int wm = (w & 1) * 64;
    const int wn = (w >> 1) * 32;
    float acc[4][4][4] = {};

    for (int c = 0; c < 8; c++) {
        const int k0 = c * 64;
        __syncthreads();
        // A: img fp32 -> inline split bf16 hi/lo, 128 rows x 64 cols
        #pragma unroll
        for (int it = 0; it < 4; it++) {
            int idx = it * 256 + tid;
            int r = idx >> 3, j8 = idx & 7;
            const float* src = img + (size_t)(m0 + r) * D_ + k0 + j8 * 8;
            float v[8];
            *(float4*)&v[0] = *(const float4*)src;
            *(float4*)&v[4] = *(const float4*)(src + 4);
            uint4 hi, lo;
            split_f8(v, hi, lo);
            uint32_t off = SWZ((uint32_t)(r * 128 + j8 * 16));
            *(uint4*)(sm + MM_AHI + off) = hi;
            *(uint4*)(sm + MM_ALO + off) = lo;
        }
        // B: pre-split Wx
        #pragma unroll
        for (int it = 0; it < 4; it++) {
            int idx = it * 256 + tid;
            int r = idx >> 3, j8 = idx & 7;
            uint32_t off = SWZ((uint32_t)(r * 128 + j8 * 16));
            *(uint4*)(sm + MM_BHI + off) = *(const uint4*)(g_WxHi + (size_t)(n0 + r) * D_ + k0 + j8 * 8);
            *(uint4*)(sm + MM_BLO + off) = *(const uint4*)(g_WxLo + (size_t)(n0 + r) * D_ + k0 + j8 * 8);
        }
        __syncthreads();

        #pragma unroll
        for (int ks = 0; ks < 4; ks++) {
            uint32_t bh[4][2], bl[4][2];
            #pragma unroll
            for (int nj = 0; nj < 4; nj++) {
                int rr = wn + nj * 8 + (lane & 7);
                uint32_t cb = (uint32_t)(ks * 32 + ((lane >> 3) & 1) * 16);
                uint32_t ad = SWZ((uint32_t)(rr * 128) + cb);
                ldsm2(bh[nj], smb + MM_BHI + ad);
                ldsm2(bl[nj], smb + MM_BLO + ad);
            }
            #pragma unroll
            for (int mi = 0; mi < 4; mi++) {
                int rr = wm + mi * 16 + (lane & 15);
                uint32_t cb = (uint32_t)(ks * 32 + (lane >> 4) * 16);
                uint32_t ad = SWZ((uint32_t)(rr * 128) + cb);
                uint32_t ah[4], al[4];
                ldsm4(ah, smb + MM_AHI + ad);
                ldsm4(al, smb + MM_ALO + ad);
                #pragma unroll
                for (int nj = 0; nj < 4; nj++) {
                    mma16816(acc[mi][nj], ah, bh[nj]);
                    mma16816(acc[mi][nj], al, bh[nj]);
                    mma16816(acc[mi][nj], ah, bl[nj]);
                }
            }
        }
    }

    #pragma unroll
    for (int mi = 0; mi < 4; mi++) {
        int mr = m0 + wm + mi * 16 + (lane >> 2);
        int b0i = mr >> 6, t0 = mr & 63;
        int b1i = (mr + 8) >> 6, t1 = (mr + 8) & 63;
        #pragma unroll
        for (int nj = 0; nj < 4; nj++) {
            int ncl = wn + nj * 8 + (lane & 3) * 2;
            int nc = n0 + ncl;
            float bx0 = s_bx[ncl], bx1 = s_bx[ncl + 1];
            g_xProjT[(size_t)b0i * (A_ * T_) + (size_t)nc * T_ + t0]       = __float2bfloat16(acc[mi][nj][0] + bx0);
            g_xProjT[(size_t)b0i * (A_ * T_) + (size_t)(nc + 1) * T_ + t0] = __float2bfloat16(acc[mi][nj][1] + bx1);
            g_xProjT[(size_t)b1i * (A_ * T_) + (size_t)nc * T_ + t1]       = __float2bfloat16(acc[mi][nj][2] + bx0);
            g_xProjT[(size_t)b1i * (A_ * T_) + (size_t)(nc + 1) * T_ + t1] = __float2bfloat16(acc[mi][nj][3] + bx1);
        }
    }
}

// ---------------- gates + FC + sProj (128 blocks) ----------------
__global__ __launch_bounds__(256) void gates_kernel(int step,
                           const int*   __restrict__ label,
                           const float* __restrict__ bs,
                           const float* __restrict__ bhh,
                           const float* __restrict__ bfc,
                           float* __restrict__ out) {
    __shared__ float hs[4][H_];
    const int tid = threadIdx.x;
    const int b0  = blockIdx.x * 4;

    if (step > 0) {
        for (int i = tid; i < 4 * H_; i += 256) {
            int b = i >> 8, j = i & 255, row = b0 + b;
            int yp = (step == 1) ? 0 : label[row * STEPS_ + step - 1];
            const float* ep = g_embProj + (size_t)yp * H3_;
            const float* gi = g_gi + (size_t)row * H3_;
            const float* gh = g_gh + (size_t)row * H3_;
            float gir = ep[j]          + gi[j];
            float giz = ep[H_ + j]     + gi[H_ + j];
            float gin = ep[2 * H_ + j] + gi[2 * H_ + j];
            float ghr = gh[j]          + bhh[j];
            float ghz = gh[H_ + j]     + bhh[H_ + j];
            float ghn = gh[2 * H_ + j] + bhh[2 * H_ + j];
            float r  = fma_sigmoid(gir + ghr);
            float zz = fma_sigmoid(giz + ghz);
            float nn = fma_tanh(gin + r * ghn);
            float hp = g_h[(size_t)row * H_ + j];
            float hn = (1.0f - zz) * nn + zz * hp;
            hs[b][j] = hn;
            g_h[(size_t)row * H_ + j] = hn;
            __nv_bfloat16 hh = __float2bfloat16(hn);
            g_hHi[(size_t)row * H_ + j] = hh;
            g_hLo[(size_t)row * H_ + j] = __float2bfloat16(hn - __bfloat162float(hh));
        }
        __syncthreads();
        for (int idx = tid; idx < 4 * C_; idx += 256) {
            int b = idx / C_, c = idx - b * C_;
            float acc = bfc[c];
            #pragma unroll 8
            for (int k = 0; k < H_; k++) acc += g_WfcT[k * C_ + c] * hs[b][k];
            out[((size_t)(b0 + b) * STEPS_ + step - 1) * C_ + c] = acc;
        }
        if (step >= STEPS_) return;
        {
            int a = tid;
            float a0 = 0.f, a1 = 0.f, a2 = 0.f, a3 = 0.f;
            #pragma unroll 4
            for (int k = 0; k < H_; k++) {
                float wv = g_WsT[k * A_ + a];
                a0 += wv * hs[0][k]; a1 += wv * hs[1][k];
                a2 += wv * hs[2][k]; a3 += wv * hs[3][k];
            }
            float bb = bs[a];
            g_sp[(size_t)(b0 + 0) * A_ + a] = a0 + bb;
            g_sp[(size_t)(b0 + 1) * A_ + a] = a1 + bb;
            g_sp[(size_t)(b0 + 2) * A_ + a] = a2 + bb;
            g_sp[(size_t)(b0 + 3) * A_ + a] = a3 + bb;
        }
    } else {
        for (int i = tid; i < 4 * A_; i += 256)
            g_sp[(size_t)b0 * A_ + i] = bs[i & 255];
    }
}

// ---------------- fused: gh GEMM (blocks 0..95) + ctx (blocks 96..607) ----------------
__global__ __launch_bounds__(256) void ctxgh_kernel(const float* __restrict__ img,
                                                    const float* __restrict__ Ww,
                                                    const float* __restrict__ bw) {
    __shared__ SMU su;
    const int tid = threadIdx.x;

    if (blockIdx.x < 96) {
        int t = blockIdx.x;                  // gh = h @ Whh^T (longest chains first)
        int mt = t / 12, nt = t % 12;
        tile_gemm64(&su.g, g_hHi, g_hLo, H_, g_WhhHi, g_WhhLo, H_,
                    mt * 64, nt * 64, 4, g_gh);
        return;
    }

    const int b = blockIdx.x - 96;
    su.c.sp[tid] = g_sp[(size_t)b * A_ + tid];
    su.c.ww[tid] = Ww[tid];
    __syncthreads();

    // ---- scores: thread = (a-group ag 0..31, t-octet tg 0..7), uint4 loads ----
    {
        const int ag = tid >> 3;
        const int tg = tid & 7;
        float acc[8] = {};
        const __nv_bfloat16* xpb = g_xProjT + (size_t)b * (A_ * T_) + tg * 8;
        #pragma unroll
        for (int j = 0; j < 8; j++) {
            int a = ag + 32 * j;
            float spa = su.c.sp[a];
            float wwa = su.c.ww[a];
            uint4 v = *(const uint4*)(xpb + (size_t)a * T_);
            const __nv_bfloat162* pv = (const __nv_bfloat162*)&v;
            #pragma unroll
            for (int k = 0; k < 4; k++) {
                float2 f = __bfloat1622float2(pv[k]);
                acc[2 * k]     += tanh_s(spa + f.x) * wwa;
                acc[2 * k + 1] += tanh_s(spa + f.y) * wwa;
            }
        }
        #pragma unroll
        for (int k = 0; k < 8; k++) su.c.part[tg * 8 + k][ag] = acc[k];
    }
    __syncthreads();
    if (tid < T_) {
        float s = bw[0];
        #pragma unroll 8
        for (int g = 0; g < 32; g++) s += su.c.part[tid][g];
        su.c.vb[tid] = s;
    }
    __syncthreads();
    if (tid < 32) {
        float v0 = su.c.vb[tid], v1 = su.c.vb[tid + 32];
        float m = warp_max(fmaxf(v0, v1));
        float e0 = __expf(v0 - m), e1 = __expf(v1 - m);
        float s = warp_sum(e0 + e1);
        float inv = 1.0f / s;
        su.c.al[tid]      = e0 * inv;
        su.c.al[tid + 32] = e1 * inv;
    }
    __syncthreads();

    // ---- ctx = alpha @ img: fp32 float4 loads, 2 t-halves ----
    {
        const int dq = tid & 127;           // float4 index over D
        const int th = tid >> 7;            // t half
        const float4* ib = (const float4*)img + (size_t)b * T_ * 128 + dq;
        float4 acc = {0.f, 0.f, 0.f, 0.f};
        const int tb = th * 32;
        #pragma unroll 8
        for (int t = tb; t < tb + 32; t++) {
            float a = su.c.al[t];
            float4 iv = ib[(size_t)t * 128];
            acc.x += a * iv.x; acc.y += a * iv.y;
            acc.z += a * iv.z; acc.w += a * iv.w;
        }
        float4* tmp = (float4*)su.c.part;   // reuse: 128 float4 = 2KB
        if (th == 1) tmp[dq] = acc;
        __syncthreads();
        if (th == 0) {
            float4 o = tmp[dq];
            acc.x += o.x; acc.y += o.y; acc.z += o.z; acc.w += o.w;
            float v[4] = {acc.x, acc.y, acc.z, acc.w};
            __nv_bfloat16 hi[4], lo[4];
            #pragma unroll
            for (int k = 0; k < 4; k++) {
                hi[k] = __float2bfloat16(v[k]);
                lo[k] = __float2bfloat16(v[k] - __bfloat162float(hi[k]));
            }
            *(uint2*)(g_ctxHi + (size_t)b * D_ + dq * 4) = *(uint2*)hi;
            *(uint2*)(g_ctxLo + (size_t)b * D_ + dq * 4) = *(uint2*)lo;
        }
    }
}

// ---------------- gi GEMM (96 blocks, 64x64 tiles, K=512) ----------------
__global__ __launch_bounds__(256) void gi_kernel() {
    __shared__ GemmBuf gb;
    int t = blockIdx.x;
    int mt = t / 12, nt = t % 12;
    tile_gemm64(&gb, g_ctxHi, g_ctxLo, D_, g_WicHi, g_WicLo, D_,
                mt * 64, nt * 64, 8, g_gi);
}

// ---------------- host launch ----------------
extern "C" void kernel_launch(void* const* d_in, const int* in_sizes, int n_in,
                              void* d_out, int out_size) {
    const float* img   = (const float*)d_in[0];
    const int*   label = (const int*)  d_in[1];
    const float* Wx    = (const float*)d_in[2];
    const float* bx    = (const float*)d_in[3];
    const float* Ws    = (const float*)d_in[4];
    const float* bs    = (const float*)d_in[5];
    const float* Ww    = (const float*)d_in[6];
    const float* bw    = (const float*)d_in[7];
    const float* emb   = (const float*)d_in[8];
    const float* Wih   = (const float*)d_in[9];
    const float* bih   = (const float*)d_in[10];
    const float* Whh   = (const float*)d_in[11];
    const float* bhh   = (const float*)d_in[12];
    const float* Wfc   = (const float*)d_in[13];
    const float* bfc   = (const float*)d_in[14];
    float* out = (float*)d_out;

    static bool attr_done = false;
    if (!attr_done) {
        cudaFuncSetAttribute(xproj_mma_kernel, cudaFuncAttributeMaxDynamicSharedMemorySize, MM_DYN);
        attr_done = true;
    }

    setup_kernel<<<512, 256>>>(Ws, Wfc, Wih, Wx, Whh);
    embproj_kernel<<<C_ + 1, 256>>>(emb, bih);

    dim3 gx(2, 256);
    xproj_mma_kernel<<<gx, 256, MM_DYN>>>(img, bx);

    for (int s = 0; s < STEPS_; s++) {
        gates_kernel<<<128, 256>>>(s, label, bs, bhh, bfc, out);
        ctxgh_kernel<<<96 + 512, 256>>>(img, Ww, bw);
        gi_kernel<<<96, 256>>>();
    }
    gates_kernel<<<128, 256>>>(STEPS_, label, bs, bhh, bfc, out);
}

// round 16
// speedup vs baseline: 1.0958x; 1.0958x over previous
#include <cuda_runtime.h>
#include <cuda_bf16.h>
#include <cstdint>

#define B_ 512
#define T_ 64
#define D_ 512
#define H_ 256
#define A_ 256
#define C_ 96
#define STEPS_ 26
#define H3_ 768

// ---------------- device scratch ----------------
__device__ __nv_bfloat16 g_xProjT[(size_t)B_ * A_ * T_];   // [B, A, T] bf16
__device__ float g_h[B_ * H_];
__device__ float g_sp[B_ * A_];
__device__ float g_gi[B_ * H3_];
__device__ float g_gh[B_ * H3_];
__device__ float g_WsT[H_ * A_];
__device__ float g_WfcT[H_ * C_];
__device__ float g_WihEmbT[A_ * H3_];
__device__ float g_embProj[(C_ + 1) * H3_];
__device__ __nv_bfloat16 g_WxHi[A_ * D_],  g_WxLo[A_ * D_];
__device__ __nv_bfloat16 g_WicHi[H3_ * D_], g_WicLo[H3_ * D_];
__device__ __nv_bfloat16 g_WhhHi[H3_ * H_], g_WhhLo[H3_ * H_];
__device__ __nv_bfloat16 g_ctxHi[B_ * D_],  g_ctxLo[B_ * D_];
__device__ __nv_bfloat16 g_hHi[B_ * H_],   g_hLo[B_ * H_];

// ---------------- math helpers ----------------
__device__ __forceinline__ float fma_tanh(float x) {
    x = fminf(3.2f, fmaxf(-3.2f, x));
    float u = x * x;
    float num = x * (945.0f + u * (105.0f + u));
    float den = 945.0f + u * (420.0f + u * 15.0f);
    float y = 1.0582e-3f + u * (-2.1408e-4f + u * 1.2184e-5f);
    y = y * (2.0f - den * y);
    y = y * (2.0f - den * y);
    y = y * (2.0f - den * y);
    return num * y;
}
__device__ __forceinline__ float fma_sigmoid(float x) {
    return 0.5f + 0.5f * fma_tanh(0.5f * x);
}
// score tanh: args tightly bounded -> clamp 1.5, CF-Pade [105+10u]/[105+45u+u^2]
__device__ __forceinline__ float tanh_s(float x) {
    x = fminf(1.5f, fmaxf(-1.5f, x));
    float u = x * x;
    float num = 105.0f + 10.0f * u;
    float den = 105.0f + u * (45.0f + u);
    float y = 9.5238e-3f + u * (-3.5187e-3f + 6.1742e-4f * u);
    y = y * (2.0f - den * y);
    y = y * (2.0f - den * y);
    return x * num * y;
}
__device__ __forceinline__ float warp_sum(float v) {
    #pragma unroll
    for (int o = 16; o; o >>= 1) v += __shfl_xor_sync(0xffffffffu, v, o);
    return v;
}
__device__ __forceinline__ float warp_max(float v) {
    #pragma unroll
    for (int o = 16; o; o >>= 1) v = fmaxf(v, __shfl_xor_sync(0xffffffffu, v, o));
    return v;
}

// ---------------- mma helpers ----------------
__device__ __forceinline__ uint32_t smem_addr_u32(const void* p) {
    uint32_t a;
    asm("{ .reg .u64 t; cvta.to.shared.u64 t, %1; cvt.u32.u64 %0, t; }" : "=r"(a) : "l"(p));
    return a;
}
__device__ __forceinline__ void ldsm4(uint32_t a[4], uint32_t addr) {
    asm volatile("ldmatrix.sync.aligned.m8n8.x4.shared.b16 {%0,%1,%2,%3}, [%4];"
        : "=r"(a[0]), "=r"(a[1]), "=r"(a[2]), "=r"(a[3]) : "r"(addr));
}
__device__ __forceinline__ void ldsm2(uint32_t b[2], uint32_t addr) {
    asm volatile("ldmatrix.sync.aligned.m8n8.x2.shared.b16 {%0,%1}, [%2];"
        : "=r"(b[0]), "=r"(b[1]) : "r"(addr));
}
__device__ __forceinline__ void mma16816(float c[4], const uint32_t a[4], const uint32_t b[2]) {
    asm volatile("mma.sync.aligned.m16n8k16.row.col.f32.bf16.bf16.f32 "
        "{%0,%1,%2,%3}, {%4,%5,%6,%7}, {%8,%9}, {%0,%1,%2,%3};"
        : "+f"(c[0]), "+f"(c[1]), "+f"(c[2]), "+f"(c[3])
        : "r"(a[0]), "r"(a[1]), "r"(a[2]), "r"(a[3]), "r"(b[0]), "r"(b[1]));
}
#define SWZ(o) ((o) ^ (((o) >> 3) & 0x70))

__device__ __forceinline__ void split_f8(const float* v, uint4& hi, uint4& lo) {
    __nv_bfloat162* hp = (__nv_bfloat162*)&hi;
    __nv_bfloat162* lp = (__nv_bfloat162*)&lo;
    #pragma unroll
    for (int j = 0; j < 4; j++) {
        float x = v[2 * j], y = v[2 * j + 1];
        __nv_bfloat16 hx = __float2bfloat16(x), hy = __float2bfloat16(y);
        hp[j].x = hx; hp[j].y = hy;
        lp[j].x = __float2bfloat16(x - __bfloat162float(hx));
        lp[j].y = __float2bfloat16(y - __bfloat162float(hy));
    }
}

// ---------------- shared-mem layouts ----------------
struct GemmBuf {                       // 32 KB
    __nv_bfloat16 tA[2][64 * 64];
    __nv_bfloat16 tB[2][64 * 64];
};
struct CtxBuf {
    float sp[A_];
    float ww[A_];
    float part[64][33];                // score partials [t][a-group]; reused as float4 tmp
    float vb[T_];
    float al[T_];
};

// ---------------- 64x64 tile GEMM ----------------
__device__ __forceinline__ void tile_gemm64(GemmBuf* s,
    const __nv_bfloat16* __restrict__ Ahi, const __nv_bfloat16* __restrict__ Alo, int lda,
    const __nv_bfloat16* __restrict__ Bhi, const __nv_bfloat16* __restrict__ Blo, int ldb,
    int m0, int n0, int kch, float* __restrict__ Cout)
{
    const int tid = threadIdx.x;
    const int lane = tid & 31;
    const int w = tid >> 5;
    const int wm = (w & 1) * 32;
    const int wn = (w >> 1) * 16;
    uint32_t sa = smem_addr_u32(s->tA);
    uint32_t sb = smem_addr_u32(s->tB);
    char* pa = (char*)s->tA;
    char* pb = (char*)s->tB;

    float acc[2][2][4] = {};
    for (int c = 0; c < kch; c++) {
        const int k0 = c * 64;
        __syncthreads();
        #pragma unroll
        for (int i = tid; i < 512; i += 256) {
            int r = i >> 3, j8 = i & 7;
            uint32_t off = SWZ((uint32_t)(r * 128 + j8 * 16));
            *(uint4*)(pa + off)        = *(const uint4*)(Ahi + (size_t)(m0 + r) * lda + k0 + j8 * 8);
            *(uint4*)(pa + 8192 + off) = *(const uint4*)(Alo + (size_t)(m0 + r) * lda + k0 + j8 * 8);
            *(uint4*)(pb + off)        = *(const uint4*)(Bhi + (size_t)(n0 + r) * ldb + k0 + j8 * 8);
            *(uint4*)(pb + 8192 + off) = *(const uint4*)(Blo + (size_t)(n0 + r) * ldb + k0 + j8 * 8);
        }
        __syncthreads();

        #pragma unroll
        for (int ks = 0; ks < 4; ks++) {
            uint32_t bh[2][2], bl[2][2];
            #pragma unroll
            for (int nj = 0; nj < 2; nj++) {
                int rr = wn + nj * 8 + (lane & 7);
                uint32_t cb = (uint32_t)(ks * 32 + ((lane >> 3) & 1) * 16);
                uint32_t ad = SWZ((uint32_t)(rr * 128) + cb);
                ldsm2(bh[nj], sb + ad);
                ldsm2(bl[nj], sb + 8192 + ad);
            }
            #pragma unroll
            for (int mi = 0; mi < 2; mi++) {
                int rr = wm + mi * 16 + (lane & 15);
                uint32_t cb = (uint32_t)(ks * 32 + (lane >> 4) * 16);
                uint32_t ad = SWZ((uint32_t)(rr * 128) + cb);
                uint32_t ah[4], al[4];
                ldsm4(ah, sa + ad);
                ldsm4(al, sa + 8192 + ad);
                #pragma unroll
                for (int nj = 0; nj < 2; nj++) {
                    mma16816(acc[mi][nj], ah, bh[nj]);
                    mma16816(acc[mi][nj], al, bh[nj]);
                    mma16816(acc[mi][nj], ah, bl[nj]);
                }
            }
        }
    }

    #pragma unroll
    for (int mi = 0; mi < 2; mi++) {
        int mr = m0 + wm + mi * 16 + (lane >> 2);
        #pragma unroll
        for (int nj = 0; nj < 2; nj++) {
            int nc = n0 + wn + nj * 8 + (lane & 3) * 2;
            float2 o0 = {acc[mi][nj][0], acc[mi][nj][1]};
            float2 o1 = {acc[mi][nj][2], acc[mi][nj][3]};
            *(float2*)(Cout + (size_t)mr * H3_ + nc) = o0;
            *(float2*)(Cout + (size_t)(mr + 8) * H3_ + nc) = o1;
        }
    }
}

// ---------------- setup ----------------
__global__ void setup_kernel(const float* __restrict__ Ws,
                             const float* __restrict__ Wfc,
                             const float* __restrict__ Wih,
                             const float* __restrict__ Wx,
                             const float* __restrict__ Whh) {
    int idx = blockIdx.x * 256 + threadIdx.x;
    int stride = gridDim.x * 256;
    for (int i = idx; i < B_ * H_; i += stride) {
        g_h[i] = 0.0f;
        g_hHi[i] = __float2bfloat16(0.0f);
        g_hLo[i] = __float2bfloat16(0.0f);
    }
    for (int i = idx; i < H_ * A_; i += stride) {
        int k = i >> 8, a = i & 255;
        g_WsT[i] = Ws[a * H_ + k];
    }
    for (int i = idx; i < H_ * C_; i += stride) {
        int k = i / C_, c = i - k * C_;
        g_WfcT[i] = Wfc[c * H_ + k];
    }
    for (int i = idx; i < A_ * H3_; i += stride) {
        int k = i / H3_, n = i - k * H3_;
        g_WihEmbT[i] = Wih[n * (D_ + A_) + k];
    }
    for (int i = idx; i < A_ * D_; i += stride) {
        float x = Wx[i];
        __nv_bfloat16 h = __float2bfloat16(x);
        g_WxHi[i] = h;
        g_WxLo[i] = __float2bfloat16(x - __bfloat162float(h));
    }
    for (int i = idx; i < H3_ * D_; i += stride) {
        int n = i >> 9, k = i & 511;
        float x = Wih[n * (D_ + A_) + A_ + k];
        __nv_bfloat16 h = __float2bfloat16(x);
        g_WicHi[i] = h;
        g_WicLo[i] = __float2bfloat16(x - __bfloat162float(h));
    }
    for (int i = idx; i < H3_ * H_; i += stride) {
        float x = Whh[i];
        __nv_bfloat16 h = __float2bfloat16(x);
        g_WhhHi[i] = h;
        g_WhhLo[i] = __float2bfloat16(x - __bfloat162float(h));
    }
}

__global__ __launch_bounds__(256) void embproj_kernel(const float* __restrict__ emb,
                                                      const float* __restrict__ bih) {
    __shared__ float es[A_];
    int y = blockIdx.x, tid = threadIdx.x;
    es[tid] = emb[y * A_ + tid];
    __syncthreads();
    for (int nn = tid; nn < H3_; nn += 256) {
        float acc = bih[nn];
        #pragma unroll 8
        for (int k = 0; k < A_; k++) acc += g_WihEmbT[k * H3_ + nn] * es[k];
        g_embProj[y * H3_ + nn] = acc;
    }
}

// ---------------- xproj (mma.sync, M=128/N=128, inline A split, bf16 output) ----
#define MM_AHI 0
#define MM_ALO 16384
#define MM_BHI 32768
#define MM_BLO 49152
#define MM_DYN (65536 + 1024)

__global__ __launch_bounds__(256, 1) void xproj_mma_kernel(const float* __restrict__ img,
                                                           const float* __restrict__ bx) {
    extern __shared__ char dynsm[];
    __shared__ float s_bx[128];
    const int tid = threadIdx.x;
    const int lane = tid & 31;
    const int w = tid >> 5;
    const int n0 = blockIdx.x * 128;
    const int m0 = blockIdx.y * 128;

    uint32_t dynb = smem_addr_u32(dynsm);
    uint32_t smb = (dynb + 1023) & ~1023u;
    char* sm = dynsm + (smb - dynb);

    if (tid < 128) s_bx[tid] = bx[n0 + tid];

    const int wm = (w & 1) * 64;
    const int wn = (w >> 1) * 32;
    float acc[4][4][4] = {};

    for (int c = 0; c < 8; c++) {
        const int k0 = c * 64;
        __syncthreads();
        #pragma unroll
        for (int it = 0; it < 4; it++) {
            int idx = it * 256 + tid;
            int r = idx >> 3, j8 = idx & 7;
            const float* src = img + (size_t)(m0 + r) * D_ + k0 + j8 * 8;
            float v[8];
            *(float4*)&v[0] = *(const float4*)src;
            *(float4*)&v[4] = *(const float4*)(src + 4);
            uint4 hi, lo;
            split_f8(v, hi, lo);
            uint32_t off = SWZ((uint32_t)(r * 128 + j8 * 16));
            *(uint4*)(sm + MM_AHI + off) = hi;
            *(uint4*)(sm + MM_ALO + off) = lo;
        }
        #pragma unroll
        for (int it = 0; it < 4; it++) {
            int idx = it * 256 + tid;
            int r = idx >> 3, j8 = idx & 7;
            uint32_t off = SWZ((uint32_t)(r * 128 + j8 * 16));
            *(uint4*)(sm + MM_BHI + off) = *(const uint4*)(g_WxHi + (size_t)(n0 + r) * D_ + k0 + j8 * 8);
            *(uint4*)(sm + MM_BLO + off) = *(const uint4*)(g_WxLo + (size_t)(n0 + r) * D_ + k0 + j8 * 8);
        }
        __syncthreads();

        #pragma unroll
        for (int ks = 0; ks < 4; ks++) {
            uint32_t bh[4][2], bl[4][2];
            #pragma unroll
            for (int nj = 0; nj < 4; nj++) {
                int rr = wn + nj * 8 + (lane & 7);
                uint32_t cb = (uint32_t)(ks * 32 + ((lane >> 3) & 1) * 16);
                uint32_t ad = SWZ((uint32_t)(rr * 128) + cb);
                ldsm2(bh[nj], smb + MM_BHI + ad);
                ldsm2(bl[nj], smb + MM_BLO + ad);
            }
            #pragma unroll
            for (int mi = 0; mi < 4; mi++) {
                int rr = wm + mi * 16 + (lane & 15);
                uint32_t cb = (uint32_t)(ks * 32 + (lane >> 4) * 16);
                uint32_t ad = SWZ((uint32_t)(rr * 128) + cb);
                uint32_t ah[4], al[4];
                ldsm4(ah, smb + MM_AHI + ad);
                ldsm4(al, smb + MM_ALO + ad);
                #pragma unroll
                for (int nj = 0; nj < 4; nj++) {
                    mma16816(acc[mi][nj], ah, bh[nj]);
                    mma16816(acc[mi][nj], al, bh[nj]);
                    mma16816(acc[mi][nj], ah, bl[nj]);
                }
            }
        }
    }

    #pragma unroll
    for (int mi = 0; mi < 4; mi++) {
        int mr = m0 + wm + mi * 16 + (lane >> 2);
        int b0i = mr >> 6, t0 = mr & 63;
        int b1i = (mr + 8) >> 6, t1 = (mr + 8) & 63;
        #pragma unroll
        for (int nj = 0; nj < 4; nj++) {
            int ncl = wn + nj * 8 + (lane & 3) * 2;
            int nc = n0 + ncl;
            float bx0 = s_bx[ncl], bx1 = s_bx[ncl + 1];
            g_xProjT[(size_t)b0i * (A_ * T_) + (size_t)nc * T_ + t0]       = __float2bfloat16(acc[mi][nj][0] + bx0);
            g_xProjT[(size_t)b0i * (A_ * T_) + (size_t)(nc + 1) * T_ + t0] = __float2bfloat16(acc[mi][nj][1] + bx1);
            g_xProjT[(size_t)b1i * (A_ * T_) + (size_t)nc * T_ + t1]       = __float2bfloat16(acc[mi][nj][2] + bx0);
            g_xProjT[(size_t)b1i * (A_ * T_) + (size_t)(nc + 1) * T_ + t1] = __float2bfloat16(acc[mi][nj][3] + bx1);
        }
    }
}

// ---------------- gates + FC + sProj (128 blocks) ----------------
__global__ __launch_bounds__(256) void gates_kernel(int step,
                           const int*   __restrict__ label,
                           const float* __restrict__ bs,
                           const float* __restrict__ bhh,
                           const float* __restrict__ bfc,
                           float* __restrict__ out) {
    __shared__ float hs[4][H_];
    const int tid = threadIdx.x;
    const int b0  = blockIdx.x * 4;

    if (step > 0) {
        for (int i = tid; i < 4 * H_; i += 256) {
            int b = i >> 8, j = i & 255, row = b0 + b;
            int yp = (step == 1) ? 0 : label[row * STEPS_ + step - 1];
            const float* ep = g_embProj + (size_t)yp * H3_;
            const float* gi = g_gi + (size_t)row * H3_;
            const float* gh = g_gh + (size_t)row * H3_;
            float gir = ep[j]          + gi[j];
            float giz = ep[H_ + j]     + gi[H_ + j];
            float gin = ep[2 * H_ + j] + gi[2 * H_ + j];
            float ghr = gh[j]          + bhh[j];
            float ghz = gh[H_ + j]     + bhh[H_ + j];
            float ghn = gh[2 * H_ + j] + bhh[2 * H_ + j];
            float r  = fma_sigmoid(gir + ghr);
            float zz = fma_sigmoid(giz + ghz);
            float nn = fma_tanh(gin + r * ghn);
            float hp = g_h[(size_t)row * H_ + j];
            float hn = (1.0f - zz) * nn + zz * hp;
            hs[b][j] = hn;
            g_h[(size_t)row * H_ + j] = hn;
            __nv_bfloat16 hh = __float2bfloat16(hn);
            g_hHi[(size_t)row * H_ + j] = hh;
            g_hLo[(size_t)row * H_ + j] = __float2bfloat16(hn - __bfloat162float(hh));
        }
        __syncthreads();
        for (int idx = tid; idx < 4 * C_; idx += 256) {
            int b = idx / C_, c = idx - b * C_;
            float acc = bfc[c];
            #pragma unroll 8
            for (int k = 0; k < H_; k++) acc += g_WfcT[k * C_ + c] * hs[b][k];
            out[((size_t)(b0 + b) * STEPS_ + step - 1) * C_ + c] = acc;
        }
        if (step >= STEPS_) return;
        {
            int a = tid;
            float a0 = 0.f, a1 = 0.f, a2 = 0.f, a3 = 0.f;
            #pragma unroll 4
            for (int k = 0; k < H_; k++) {
                float wv = g_WsT[k * A_ + a];
                a0 += wv * hs[0][k]; a1 += wv * hs[1][k];
                a2 += wv * hs[2][k]; a3 += wv * hs[3][k];
            }
            float bb = bs[a];
            g_sp[(size_t)(b0 + 0) * A_ + a] = a0 + bb;
            g_sp[(size_t)(b0 + 1) * A_ + a] = a1 + bb;
            g_sp[(size_t)(b0 + 2) * A_ + a] = a2 + bb;
            g_sp[(size_t)(b0 + 3) * A_ + a] = a3 + bb;
        }
    } else {
        for (int i = tid; i < 4 * A_; i += 256)
            g_sp[(size_t)b0 * A_ + i] = bs[i & 255];
    }
}

// ---------------- ctx (512 blocks, pure) ----------------
__global__ __launch_bounds__(256) void ctx_kernel(const float* __restrict__ img,
                                                  const float* __restrict__ Ww,
                                                  const float* __restrict__ bw) {
    __shared__ CtxBuf c;
    const int tid = threadIdx.x;
    const int b = blockIdx.x;

    c.sp[tid] = g_sp[(size_t)b * A_ + tid];
    c.ww[tid] = Ww[tid];
    __syncthreads();

    // ---- scores: thread = (a-group ag 0..31, t-octet tg 0..7), uint4 loads ----
    {
        const int ag = tid >> 3;
        const int tg = tid & 7;
        float acc[8] = {};
        const __nv_bfloat16* xpb = g_xProjT + (size_t)b * (A_ * T_) + tg * 8;
        #pragma unroll
        for (int j = 0; j < 8; j++) {
            int a = ag + 32 * j;
            float spa = c.sp[a];
            float wwa = c.ww[a];
            uint4 v = *(const uint4*)(xpb + (size_t)a * T_);
            const __nv_bfloat162* pv = (const __nv_bfloat162*)&v;
            #pragma unroll
            for (int k = 0; k < 4; k++) {
                float2 f = __bfloat1622float2(pv[k]);
                acc[2 * k]     += tanh_s(spa + f.x) * wwa;
                acc[2 * k + 1] += tanh_s(spa + f.y) * wwa;
            }
        }
        #pragma unroll
        for (int k = 0; k < 8; k++) c.part[tg * 8 + k][ag] = acc[k];
    }
    __syncthreads();
    if (tid < T_) {
        float s = bw[0];
        #pragma unroll 8
        for (int g = 0; g < 32; g++) s += c.part[tid][g];
        c.vb[tid] = s;
    }
    __syncthreads();
    if (tid < 32) {
        float v0 = c.vb[tid], v1 = c.vb[tid + 32];
        float m = warp_max(fmaxf(v0, v1));
        float e0 = __expf(v0 - m), e1 = __expf(v1 - m);
        float s = warp_sum(e0 + e1);
        float inv = 1.0f / s;
        c.al[tid]      = e0 * inv;
        c.al[tid + 32] = e1 * inv;
    }
    __syncthreads();

    // ---- ctx = alpha @ img: fp32 float4 loads, 2 t-halves ----
    {
        const int dq = tid & 127;
        const int th = tid >> 7;
        const float4* ib = (const float4*)img + (size_t)b * T_ * 128 + dq;
        float4 acc = {0.f, 0.f, 0.f, 0.f};
        const int tb = th * 32;
        #pragma unroll 8
        for (int t = tb; t < tb + 32; t++) {
            float a = c.al[t];
            float4 iv = ib[(size_t)t * 128];
            acc.x += a * iv.x; acc.y += a * iv.y;
            acc.z += a * iv.z; acc.w += a * iv.w;
        }
        float4* tmp = (float4*)c.part;
        if (th == 1) tmp[dq] = acc;
        __syncthreads();
        if (th == 0) {
            float4 o = tmp[dq];
            acc.x += o.x; acc.y += o.y; acc.z += o.z; acc.w += o.w;
            float v[4] = {acc.x, acc.y, acc.z, acc.w};
            __nv_bfloat16 hi[4], lo[4];
            #pragma unroll
            for (int k = 0; k < 4; k++) {
                hi[k] = __float2bfloat16(v[k]);
                lo[k] = __float2bfloat16(v[k] - __bfloat162float(hi[k]));
            }
            *(uint2*)(g_ctxHi + (size_t)b * D_ + dq * 4) = *(uint2*)hi;
            *(uint2*)(g_ctxLo + (size_t)b * D_ + dq * 4) = *(uint2*)lo;
        }
    }
}

// ---------------- gemm: gi tiles (blocks 0..95) + gh tiles (96..191) ----------------
__global__ __launch_bounds__(256) void gemm_kernel() {
    __shared__ GemmBuf gb;
    int t = blockIdx.x;
    if (t < 96) {
        int mt = t / 12, nt = t % 12;
        tile_gemm64(&gb, g_ctxHi, g_ctxLo, D_, g_WicHi, g_WicLo, D_,
                    mt * 64, nt * 64, 8, g_gi);
    } else {
        t -= 96;
        int mt = t / 12, nt = t % 12;
        tile_gemm64(&gb, g_hHi, g_hLo, H_, g_WhhHi, g_WhhLo, H_,
                    mt * 64, nt * 64, 4, g_gh);
    }
}

// ---------------- host launch ----------------
extern "C" void kernel_launch(void* const* d_in, const int* in_sizes, int n_in,
                              void* d_out, int out_size) {
    const float* img   = (const float*)d_in[0];
    const int*   label = (const int*)  d_in[1];
    const float* Wx    = (const float*)d_in[2];
    const float* bx    = (const float*)d_in[3];
    const float* Ws    = (const float*)d_in[4];
    const float* bs    = (const float*)d_in[5];
    const float* Ww    = (const float*)d_in[6];
    const float* bw    = (const float*)d_in[7];
    const float* emb   = (const float*)d_in[8];
    const float* Wih   = (const float*)d_in[9];
    const float* bih   = (const float*)d_in[10];
    const float* Whh   = (const float*)d_in[11];
    const float* bhh   = (const float*)d_in[12];
    const float* Wfc   = (const float*)d_in[13];
    const float* bfc   = (const float*)d_in[14];
    float* out = (float*)d_out;

    static bool attr_done = false;
    if (!attr_done) {
        cudaFuncSetAttribute(xproj_mma_kernel, cudaFuncAttributeMaxDynamicSharedMemorySize, MM_DYN);
        attr_done = true;
    }

    setup_kernel<<<512, 256>>>(Ws, Wfc, Wih, Wx, Whh);
    embproj_kernel<<<C_ + 1, 256>>>(emb, bih);

    dim3 gx(2, 256);
    xproj_mma_kernel<<<gx, 256, MM_DYN>>>(img, bx);

    for (int s = 0; s < STEPS_; s++) {
        gates_kernel<<<128, 256>>>(s, label, bs, bhh, bfc, out);
        ctx_kernel<<<512, 256>>>(img, Ww, bw);
        gemm_kernel<<<192, 256>>>();
    }
    gates_kernel<<<128, 256>>>(STEPS_, label, bs, bhh, bfc, out);
}